// round 12
// baseline (speedup 1.0000x reference)
#include <cuda_runtime.h>
#include <math.h>

#define SEQ 512
#define BSZ 64
#define INP 512
#define HID 1024
#define NCTA 128                 // 2 b-chunks x 64 j-chunks
#define SMEM3 (16384 * 4 + 256 * 8 * 8)   // W tile 64KB + partials 16KB

typedef unsigned long long ull;

__device__ unsigned g_cnt[SEQ];

__global__ void zero_cnt_kernel() { g_cnt[threadIdx.x] = 0u; }

__device__ __forceinline__ ull ffma2(ull a, ull b, ull c) {
    ull d;
    asm("fma.rn.f32x2 %0, %1, %2, %3;" : "=l"(d) : "l"(a), "l"(b), "l"(c));
    return d;
}
__device__ __forceinline__ ull dup2(float x) {
    ull r;
    asm("mov.b64 %0, {%1, %1};" : "=l"(r) : "r"(__float_as_uint(x)));
    return r;
}
__device__ __forceinline__ unsigned ld_acq(const unsigned* p) {
    unsigned v;
    asm volatile("ld.acquire.gpu.global.u32 %0, [%1];"
                 : "=r"(v) : "l"(p) : "memory");
    return v;
}
__device__ __forceinline__ void arrive_release(unsigned* p) {
    asm volatile("red.release.gpu.global.add.u32 [%0], 1;"
                 :: "l"(p) : "memory");
}
// Fast accurate tanh: t = e^{2x}; tanh = (t-1)/(t+1).
__device__ __forceinline__ float tanh_fast(float x) {
    x = fminf(fmaxf(x, -10.0f), 10.0f);
    float e;
    asm("ex2.approx.f32 %0, %1;" : "=f"(e) : "f"(x * 2.8853900817779268f));
    float r;
    asm("rcp.approx.f32 %0, %1;" : "=f"(r) : "f"(e + 1.0f));
    return (e - 1.0f) * r;
}

// ---------------------------------------------------------------------------
// Kernel 1: C[m][n] = sum_k A[m][k]*W[n][k] + b_ih[n] + b_hh[n]   (FFMA2)
// Tile 64x64x16, 128 threads, thread tile 8m x 4n (m paired for f32x2).
// Writes PRE-activations for every timestep into out.
// ---------------------------------------------------------------------------
__global__ __launch_bounds__(128) void gemm_xw_kernel(
    const float* __restrict__ A,
    const float* __restrict__ W,
    const float* __restrict__ b_ih,
    const float* __restrict__ b_hh,
    float* __restrict__ C)
{
    __shared__ float sA[16][68];   // [k][m]
    __shared__ float sB[16][68];   // [k][n]

    const int t  = threadIdx.x;
    const int n0 = blockIdx.x * 64;
    const int m0 = blockIdx.y * 64;
    const int tx = t & 15;
    const int ty = t >> 4;
    const int lr = t >> 1;
    const int lk = (t & 1) * 8;

    ull acc[4][4];
#pragma unroll
    for (int i = 0; i < 4; ++i)
#pragma unroll
        for (int j = 0; j < 4; ++j) acc[i][j] = 0ull;

    const float* Arow = A + (size_t)(m0 + lr) * INP + lk;
    const float* Wrow = W + (size_t)(n0 + lr) * INP + lk;

    for (int k0 = 0; k0 < INP; k0 += 16) {
        float4 a0 = *(const float4*)(Arow + k0);
        float4 a1 = *(const float4*)(Arow + k0 + 4);
        float4 w0 = *(const float4*)(Wrow + k0);
        float4 w1 = *(const float4*)(Wrow + k0 + 4);
        __syncthreads();
        sA[lk + 0][lr] = a0.x; sA[lk + 1][lr] = a0.y;
        sA[lk + 2][lr] = a0.z; sA[lk + 3][lr] = a0.w;
        sA[lk + 4][lr] = a1.x; sA[lk + 5][lr] = a1.y;
        sA[lk + 6][lr] = a1.z; sA[lk + 7][lr] = a1.w;
        sB[lk + 0][lr] = w0.x; sB[lk + 1][lr] = w0.y;
        sB[lk + 2][lr] = w0.z; sB[lk + 3][lr] = w0.w;
        sB[lk + 4][lr] = w1.x; sB[lk + 5][lr] = w1.y;
        sB[lk + 6][lr] = w1.z; sB[lk + 7][lr] = w1.w;
        __syncthreads();
#pragma unroll
        for (int k = 0; k < 16; ++k) {
            const ull* arow = (const ull*)&sA[k][ty * 8];
            ull am0 = arow[0], am1 = arow[1], am2 = arow[2], am3 = arow[3];
            float4 bv = *(const float4*)&sB[k][tx * 4];
            ull bn0 = dup2(bv.x), bn1 = dup2(bv.y);
            ull bn2 = dup2(bv.z), bn3 = dup2(bv.w);
            acc[0][0] = ffma2(am0, bn0, acc[0][0]);
            acc[0][1] = ffma2(am0, bn1, acc[0][1]);
            acc[0][2] = ffma2(am0, bn2, acc[0][2]);
            acc[0][3] = ffma2(am0, bn3, acc[0][3]);
            acc[1][0] = ffma2(am1, bn0, acc[1][0]);
            acc[1][1] = ffma2(am1, bn1, acc[1][1]);
            acc[1][2] = ffma2(am1, bn2, acc[1][2]);
            acc[1][3] = ffma2(am1, bn3, acc[1][3]);
            acc[2][0] = ffma2(am2, bn0, acc[2][0]);
            acc[2][1] = ffma2(am2, bn1, acc[2][1]);
            acc[2][2] = ffma2(am2, bn2, acc[2][2]);
            acc[2][3] = ffma2(am2, bn3, acc[2][3]);
            acc[3][0] = ffma2(am3, bn0, acc[3][0]);
            acc[3][1] = ffma2(am3, bn1, acc[3][1]);
            acc[3][2] = ffma2(am3, bn2, acc[3][2]);
            acc[3][3] = ffma2(am3, bn3, acc[3][3]);
        }
    }

    float4 bi = *(const float4*)(b_ih + n0 + tx * 4);
    float4 bh = *(const float4*)(b_hh + n0 + tx * 4);
    float4 bias;
    bias.x = bi.x + bh.x; bias.y = bi.y + bh.y;
    bias.z = bi.z + bh.z; bias.w = bi.w + bh.w;

#pragma unroll
    for (int i = 0; i < 8; ++i) {
        const int mp = i >> 1;
        const int sel = i & 1;
        float2 a0 = *(float2*)&acc[mp][0];
        float2 a1 = *(float2*)&acc[mp][1];
        float2 a2 = *(float2*)&acc[mp][2];
        float2 a3 = *(float2*)&acc[mp][3];
        float4 o;
        o.x = (sel ? a0.y : a0.x) + bias.x;
        o.y = (sel ? a1.y : a1.x) + bias.y;
        o.z = (sel ? a2.y : a2.x) + bias.z;
        o.w = (sel ? a3.y : a3.x) + bias.w;
        *(float4*)&C[(size_t)(m0 + ty * 8 + i) * HID + n0 + tx * 4] = o;
    }
}

// ---------------------------------------------------------------------------
// Kernel 2: tanh of timestep 0 (turn pre-act into final h0).
// ---------------------------------------------------------------------------
__global__ __launch_bounds__(256) void tanh_first_kernel(float* __restrict__ out) {
    const int b = blockIdx.x;
    const size_t off = ((size_t)b * SEQ) * HID + threadIdx.x * 4;
    float4 v = *(const float4*)(out + off);
    v.x = tanh_fast(v.x); v.y = tanh_fast(v.y);
    v.z = tanh_fast(v.z); v.w = tanh_fast(v.w);
    *(float4*)(out + off) = v;
}

// ---------------------------------------------------------------------------
// Kernel 3: persistent recurrence, NO atomics.
// CTA c: bc = c&1 (32 b), jc = c>>1 (16 j). Full K=1024 per CTA:
//   warp w owns k in [w*128, +128); lane l owns b-row b0+l, h in registers.
// W tile [1024 k][16 j] k-major in smem (64 KB). Partials reduced in smem,
// pre-act added, tanh applied, final h stored with stcg. out holds FINAL h.
// ---------------------------------------------------------------------------
__global__ __launch_bounds__(256) void rnn_step_kernel(
    const float* __restrict__ Whh,   // 1024 x 1024
    float* __restrict__ out)         // (64, 512, 1024)
{
    extern __shared__ float smem[];
    float* sW   = smem;                     // [1024][16]
    ull*   part = (ull*)(smem + 16384);     // [256][8]

    const int t  = threadIdx.x;
    const int c  = blockIdx.x;
    const int bc = c & 1;
    const int jc = c >> 1;
    const int j0 = jc * 16;
    const int b0 = bc * 32;

    // One-time W tile load, transposed to k-major [k][j].
    {
        const int j  = t & 15;
        const int kb = (t >> 4) * 64;
        const float* src = Whh + (size_t)(j0 + j) * HID + kb;
#pragma unroll
        for (int kk = 0; kk < 64; kk += 4) {
            float4 v = *(const float4*)(src + kk);
            sW[(kb + kk + 0) * 16 + j] = v.x;
            sW[(kb + kk + 1) * 16 + j] = v.y;
            sW[(kb + kk + 2) * 16 + j] = v.z;
            sW[(kb + kk + 3) * 16 + j] = v.w;
        }
    }
    __syncthreads();

    const int w  = t >> 5;           // warp: k-slice owner
    const int l  = t & 31;           // lane: b-row owner
    const int b  = b0 + l;
    const int k0 = w * 128;
    const int bh = t >> 3;           // final phase: b index (0..31)
    const int p  = t & 7;            // final phase: j-pair index (0..7)

    for (int s = 1; s < SEQ; ++s) {
        if (s >= 2) {
            if (t == 0) {
                const unsigned* q = &g_cnt[s - 1];
                while (ld_acq(q) != (unsigned)NCTA) __nanosleep(8);
            }
        }
        __syncthreads();   // step gate; also fences partial-buffer reuse

        // Pre-act for this thread's 2 outputs (written by gemm; stable).
        const size_t orow = ((size_t)(b0 + bh) * SEQ + s) * HID + j0 + 2 * p;
        float2 pa = __ldcg((const float2*)(out + orow));

        // h row for this lane (final h of step s-1), k-slice of this warp.
        const float* hrow = out + ((size_t)b * SEQ + (s - 1)) * HID + k0;

        ull acc[8];
#pragma unroll
        for (int q = 0; q < 8; ++q) acc[q] = 0ull;

        float4 c0 = __ldcg((const float4*)(hrow + 0));
        float4 c1 = __ldcg((const float4*)(hrow + 4));
#pragma unroll 4
        for (int kb = 0; kb < 128; kb += 8) {
            float4 n0 = __ldcg((const float4*)(hrow + kb + 8));
            float4 n1 = __ldcg((const float4*)(hrow + kb + 12));
            const ull* wp = (const ull*)sW + (size_t)(k0 + kb) * 8;
            float hv[8] = {c0.x, c0.y, c0.z, c0.w, c1.x, c1.y, c1.z, c1.w};
#pragma unroll
            for (int kk = 0; kk < 8; ++kk) {
                ull h2 = dup2(hv[kk]);
                const ull* wk = wp + kk * 8;
                acc[0] = ffma2(h2, wk[0], acc[0]);
                acc[1] = ffma2(h2, wk[1], acc[1]);
                acc[2] = ffma2(h2, wk[2], acc[2]);
                acc[3] = ffma2(h2, wk[3], acc[3]);
                acc[4] = ffma2(h2, wk[4], acc[4]);
                acc[5] = ffma2(h2, wk[5], acc[5]);
                acc[6] = ffma2(h2, wk[6], acc[6]);
                acc[7] = ffma2(h2, wk[7], acc[7]);
            }
            c0 = n0; c1 = n1;
        }

        // Stash this thread's partial tile (b=b0+l, 8 j-pairs).
        {
            ull* mp = part + (size_t)t * 8;
            *(ulonglong2*)(mp + 0) = make_ulonglong2(acc[0], acc[1]);
            *(ulonglong2*)(mp + 2) = make_ulonglong2(acc[2], acc[3]);
            *(ulonglong2*)(mp + 4) = make_ulonglong2(acc[4], acc[5]);
            *(ulonglong2*)(mp + 6) = make_ulonglong2(acc[6], acc[7]);
        }
        __syncthreads();

        // Final: sum the 8 warp-partials for outputs (b0+bh, j0+2p, +1),
        // add pre-act, tanh, store final h.
        {
            float sx = pa.x, sy = pa.y;
#pragma unroll
            for (int w2 = 0; w2 < 8; ++w2) {
                ull v = part[((size_t)w2 * 32 + bh) * 8 + p];
                float2 f = *(float2*)&v;
                sx += f.x; sy += f.y;
            }
            float2 hout;
            hout.x = tanh_fast(sx);
            hout.y = tanh_fast(sy);
            __stcg((float2*)(out + orow), hout);
        }

        __syncthreads();   // all stores issued before the release-arrive
        if (t == 0 && s < SEQ - 1) arrive_release(&g_cnt[s]);
    }
}

extern "C" void kernel_launch(void* const* d_in, const int* in_sizes, int n_in,
                              void* d_out, int out_size) {
    const float* x   = (const float*)d_in[0];   // (64, 512, 512)
    const float* Wih = (const float*)d_in[1];   // (1024, 512)
    const float* Whh = (const float*)d_in[2];   // (1024, 1024)
    const float* bih = (const float*)d_in[3];   // (1024,)
    const float* bhh = (const float*)d_in[4];   // (1024,)
    float* out = (float*)d_out;                 // (64, 512, 1024)

    cudaFuncSetAttribute(rnn_step_kernel,
                         cudaFuncAttributeMaxDynamicSharedMemorySize, SMEM3);

    zero_cnt_kernel<<<1, SEQ>>>();

    dim3 g1(HID / 64, (BSZ * SEQ) / 64);
    gemm_xw_kernel<<<g1, 128>>>(x, Wih, bih, bhh, out);

    tanh_first_kernel<<<BSZ, 256>>>(out);

    rnn_step_kernel<<<NCTA, 256, SMEM3>>>(Whh, out);
}

// round 14
// speedup vs baseline: 1.5673x; 1.5673x over previous
#include <cuda_runtime.h>
#include <math.h>

#define SEQ 512
#define BSZ 64
#define INP 512
#define HID 1024
#define NCTA 128                 // 2 batch-groups x 8 j-chunks x 8 k-chunks
#define PIPE_TARGET 64           // CTAs per batch-group pipeline
#define SW_STRIDE 132            // floats per k-row of W tile (128 j + pad)
#define SH_STRIDE 36             // floats per k-row of h tile (32 b + pad)
#define SMEM3 ((128 * SW_STRIDE + 128 * SH_STRIDE) * 4)

typedef unsigned long long ull;

// One padded counter per (step, batch-group).
__device__ unsigned g_cnt3[SEQ][2][32];

__global__ void zero_cnt_kernel() {            // <<<2, SEQ>>>
    g_cnt3[threadIdx.x][blockIdx.x][0] = 0u;
}

__device__ __forceinline__ ull ffma2(ull a, ull b, ull c) {
    ull d;
    asm("fma.rn.f32x2 %0, %1, %2, %3;" : "=l"(d) : "l"(a), "l"(b), "l"(c));
    return d;
}
__device__ __forceinline__ ull dup2(float x) {
    ull r;
    asm("mov.b64 %0, {%1, %1};" : "=l"(r) : "r"(__float_as_uint(x)));
    return r;
}
__device__ __forceinline__ void red_add_v4(float* p, float a, float b,
                                           float c, float d) {
    asm volatile("red.global.add.v4.f32 [%0], {%1, %2, %3, %4};"
                 :: "l"(p), "f"(a), "f"(b), "f"(c), "f"(d) : "memory");
}
__device__ __forceinline__ unsigned ld_acq(const unsigned* p) {
    unsigned v;
    asm volatile("ld.acquire.gpu.global.u32 %0, [%1];"
                 : "=r"(v) : "l"(p) : "memory");
    return v;
}
__device__ __forceinline__ void arrive_release(unsigned* p) {
    asm volatile("red.release.gpu.global.add.u32 [%0], 1;"
                 :: "l"(p) : "memory");
}
// Fast accurate tanh: t = e^{2x}; tanh = (t-1)/(t+1).
__device__ __forceinline__ float tanh_fast(float x) {
    x = fminf(fmaxf(x, -10.0f), 10.0f);
    float e;
    asm("ex2.approx.f32 %0, %1;" : "=f"(e) : "f"(x * 2.8853900817779268f));
    float r;
    asm("rcp.approx.f32 %0, %1;" : "=f"(r) : "f"(e + 1.0f));
    return (e - 1.0f) * r;
}

// ---------------------------------------------------------------------------
// Kernel 1: C[m][n] = sum_k A[m][k]*W[n][k] + b_ih[n] + b_hh[n]   (FFMA2)
// Tile 64x64x16, 128 threads, thread tile 8m x 4n, software prefetch.
// ---------------------------------------------------------------------------
__global__ __launch_bounds__(128) void gemm_xw_kernel(
    const float* __restrict__ A,
    const float* __restrict__ W,
    const float* __restrict__ b_ih,
    const float* __restrict__ b_hh,
    float* __restrict__ C)
{
    __shared__ float sA[16][68];   // [k][m]
    __shared__ float sB[16][68];   // [k][n]

    const int t  = threadIdx.x;
    const int n0 = blockIdx.x * 64;
    const int m0 = blockIdx.y * 64;
    const int tx = t & 15;
    const int ty = t >> 4;
    const int lr = t >> 1;
    const int lk = (t & 1) * 8;

    ull acc[4][4];
#pragma unroll
    for (int i = 0; i < 4; ++i)
#pragma unroll
        for (int j = 0; j < 4; ++j) acc[i][j] = 0ull;

    const float* Arow = A + (size_t)(m0 + lr) * INP + lk;
    const float* Wrow = W + (size_t)(n0 + lr) * INP + lk;

    // Preload chunk 0.
    float4 a0 = *(const float4*)(Arow + 0);
    float4 a1 = *(const float4*)(Arow + 4);
    float4 w0 = *(const float4*)(Wrow + 0);
    float4 w1 = *(const float4*)(Wrow + 4);

    for (int k0 = 0; k0 < INP; k0 += 16) {
        __syncthreads();
        sA[lk + 0][lr] = a0.x; sA[lk + 1][lr] = a0.y;
        sA[lk + 2][lr] = a0.z; sA[lk + 3][lr] = a0.w;
        sA[lk + 4][lr] = a1.x; sA[lk + 5][lr] = a1.y;
        sA[lk + 6][lr] = a1.z; sA[lk + 7][lr] = a1.w;
        sB[lk + 0][lr] = w0.x; sB[lk + 1][lr] = w0.y;
        sB[lk + 2][lr] = w0.z; sB[lk + 3][lr] = w0.w;
        sB[lk + 4][lr] = w1.x; sB[lk + 5][lr] = w1.y;
        sB[lk + 6][lr] = w1.z; sB[lk + 7][lr] = w1.w;
        __syncthreads();
        if (k0 + 16 < INP) {       // prefetch next chunk; overlaps compute
            a0 = *(const float4*)(Arow + k0 + 16);
            a1 = *(const float4*)(Arow + k0 + 20);
            w0 = *(const float4*)(Wrow + k0 + 16);
            w1 = *(const float4*)(Wrow + k0 + 20);
        }
#pragma unroll
        for (int k = 0; k < 16; ++k) {
            const ull* arow = (const ull*)&sA[k][ty * 8];
            ull am0 = arow[0], am1 = arow[1], am2 = arow[2], am3 = arow[3];
            float4 bv = *(const float4*)&sB[k][tx * 4];
            ull bn0 = dup2(bv.x), bn1 = dup2(bv.y);
            ull bn2 = dup2(bv.z), bn3 = dup2(bv.w);
            acc[0][0] = ffma2(am0, bn0, acc[0][0]);
            acc[0][1] = ffma2(am0, bn1, acc[0][1]);
            acc[0][2] = ffma2(am0, bn2, acc[0][2]);
            acc[0][3] = ffma2(am0, bn3, acc[0][3]);
            acc[1][0] = ffma2(am1, bn0, acc[1][0]);
            acc[1][1] = ffma2(am1, bn1, acc[1][1]);
            acc[1][2] = ffma2(am1, bn2, acc[1][2]);
            acc[1][3] = ffma2(am1, bn3, acc[1][3]);
            acc[2][0] = ffma2(am2, bn0, acc[2][0]);
            acc[2][1] = ffma2(am2, bn1, acc[2][1]);
            acc[2][2] = ffma2(am2, bn2, acc[2][2]);
            acc[2][3] = ffma2(am2, bn3, acc[2][3]);
            acc[3][0] = ffma2(am3, bn0, acc[3][0]);
            acc[3][1] = ffma2(am3, bn1, acc[3][1]);
            acc[3][2] = ffma2(am3, bn2, acc[3][2]);
            acc[3][3] = ffma2(am3, bn3, acc[3][3]);
        }
    }

    float4 bi = *(const float4*)(b_ih + n0 + tx * 4);
    float4 bh = *(const float4*)(b_hh + n0 + tx * 4);
    float4 bias;
    bias.x = bi.x + bh.x; bias.y = bi.y + bh.y;
    bias.z = bi.z + bh.z; bias.w = bi.w + bh.w;

#pragma unroll
    for (int i = 0; i < 8; ++i) {
        const int mp = i >> 1;
        const int sel = i & 1;
        float2 a0f = *(float2*)&acc[mp][0];
        float2 a1f = *(float2*)&acc[mp][1];
        float2 a2f = *(float2*)&acc[mp][2];
        float2 a3f = *(float2*)&acc[mp][3];
        float4 o;
        o.x = (sel ? a0f.y : a0f.x) + bias.x;
        o.y = (sel ? a1f.y : a1f.x) + bias.y;
        o.z = (sel ? a2f.y : a2f.x) + bias.z;
        o.w = (sel ? a3f.y : a3f.x) + bias.w;
        *(float4*)&C[(size_t)(m0 + ty * 8 + i) * HID + n0 + tx * 4] = o;
    }
}

// ---------------------------------------------------------------------------
// Kernel 2: persistent recurrence, 2 independent batch-group pipelines.
// CTA: bg = bid&1 (32 b), jc = (bid>>1)&7 (128 j), kc = bid>>4 (128 k).
// W_hh tile [128k][128j] in smem; h tile [128k][32b]. Thread tile 2b x 8j.
// Pipelines never interact: counters per (step, bg), fan-in 64.
// ---------------------------------------------------------------------------
__global__ __launch_bounds__(256) void rnn_step_kernel(
    const float* __restrict__ Whh,   // 1024 x 1024
    float* __restrict__ out)         // (64, 512, 1024) pre-seeded with xw+bias
{
    extern __shared__ float smem[];
    float* sW = smem;                      // [128][SW_STRIDE]
    float* sh = smem + 128 * SW_STRIDE;    // [128][SH_STRIDE]

    const int t  = threadIdx.x;
    const int bg = blockIdx.x & 1;          // batch-group (pipeline)
    const int jc = (blockIdx.x >> 1) & 7;   // 0..7 (128 j each)
    const int kc = blockIdx.x >> 4;         // 0..7 (128 k each)
    const int b0 = bg * 32;
    const int j0 = jc * 128;

    // One-time W tile load, transposed to k-major [k][j].
    {
        const int j  = t & 127;             // 0..127
        const int kh = (t >> 7) * 64;       // 0 or 64
        const float* src = Whh + (size_t)(j0 + j) * HID + kc * 128 + kh;
#pragma unroll
        for (int kk = 0; kk < 64; kk += 4) {
            float4 v = *(const float4*)(src + kk);
            sW[(kh + kk + 0) * SW_STRIDE + j] = v.x;
            sW[(kh + kk + 1) * SW_STRIDE + j] = v.y;
            sW[(kh + kk + 2) * SW_STRIDE + j] = v.z;
            sW[(kh + kk + 3) * SW_STRIDE + j] = v.w;
        }
    }
    __syncthreads();

    const int tb2 = (t & 15) * 2;     // base b of thread tile (2 of 32)
    const int tj8 = (t >> 4) * 8;     // base j of thread tile (8 of 128)
    const int fb  = t & 31;           // fill: b row (0..31)
    const int fk  = (t >> 5) * 16;    // fill: k base (16 k per thread)

    for (int s = 1; s < SEQ; ++s) {
        if (s >= 2) {
            if (t == 0) {
                const unsigned* p = &g_cnt3[s - 1][bg][0];
                while (ld_acq(p) != (unsigned)PIPE_TARGET) __nanosleep(8);
            }
            __syncthreads();
        }

        // Fill sh[k][b] = tanh_fast(pre-act[b0+b][s-1][kc*128+k]).
        {
            const float* src = out + ((size_t)((b0 + fb) * SEQ + (s - 1))) * HID
                                   + kc * 128 + fk;
            float4 v[4];
#pragma unroll
            for (int q = 0; q < 4; ++q)
                v[q] = __ldcg((const float4*)(src + q * 4));
#pragma unroll
            for (int q = 0; q < 4; ++q) {
                sh[(fk + 4 * q + 0) * SH_STRIDE + fb] = tanh_fast(v[q].x);
                sh[(fk + 4 * q + 1) * SH_STRIDE + fb] = tanh_fast(v[q].y);
                sh[(fk + 4 * q + 2) * SH_STRIDE + fb] = tanh_fast(v[q].z);
                sh[(fk + 4 * q + 3) * SH_STRIDE + fb] = tanh_fast(v[q].w);
            }
        }
        __syncthreads();

        ull acc[2][4];                 // [b][j-pair]
#pragma unroll
        for (int i = 0; i < 2; ++i)
#pragma unroll
            for (int j = 0; j < 4; ++j) acc[i][j] = 0ull;

        const float* hbase = sh + tb2;
        const float* wbase = sW + tj8;

#pragma unroll 8
        for (int k = 0; k < 128; ++k) {
            float2 hv = *(const float2*)(hbase + (size_t)k * SH_STRIDE);
            ulonglong2 wA = *(const ulonglong2*)(wbase + (size_t)k * SW_STRIDE);
            ulonglong2 wB = *(const ulonglong2*)(wbase + (size_t)k * SW_STRIDE + 4);
            ull h0 = dup2(hv.x), h1 = dup2(hv.y);
            acc[0][0] = ffma2(h0, wA.x, acc[0][0]);
            acc[0][1] = ffma2(h0, wA.y, acc[0][1]);
            acc[0][2] = ffma2(h0, wB.x, acc[0][2]);
            acc[0][3] = ffma2(h0, wB.y, acc[0][3]);
            acc[1][0] = ffma2(h1, wA.x, acc[1][0]);
            acc[1][1] = ffma2(h1, wA.y, acc[1][1]);
            acc[1][2] = ffma2(h1, wB.x, acc[1][2]);
            acc[1][3] = ffma2(h1, wB.y, acc[1][3]);
        }

        // Vectorized reduction into the pre-act buffer for step s.
#pragma unroll
        for (int i = 0; i < 2; ++i) {
            const int b = b0 + tb2 + i;
            float* row = out + ((size_t)(b * SEQ + s)) * HID + j0 + tj8;
            float2 a0 = *(float2*)&acc[i][0];
            float2 a1 = *(float2*)&acc[i][1];
            float2 a2 = *(float2*)&acc[i][2];
            float2 a3 = *(float2*)&acc[i][3];
            red_add_v4(row,     a0.x, a0.y, a1.x, a1.y);
            red_add_v4(row + 4, a2.x, a2.y, a3.x, a3.y);
        }

        // bar.sync orders all threads' red ops before t0's release-arrive.
        __syncthreads();
        if (t == 0 && s < SEQ - 1) arrive_release(&g_cnt3[s][bg][0]);
    }
}

// ---------------------------------------------------------------------------
// Kernel 3: elementwise tanh over the whole output buffer.
// ---------------------------------------------------------------------------
__global__ __launch_bounds__(256) void tanh_kernel(float* __restrict__ out) {
    size_t i = ((size_t)blockIdx.x * blockDim.x + threadIdx.x) * 4;
    float4 v = *(float4*)(out + i);
    v.x = tanh_fast(v.x); v.y = tanh_fast(v.y);
    v.z = tanh_fast(v.z); v.w = tanh_fast(v.w);
    *(float4*)(out + i) = v;
}

extern "C" void kernel_launch(void* const* d_in, const int* in_sizes, int n_in,
                              void* d_out, int out_size) {
    const float* x   = (const float*)d_in[0];   // (64, 512, 512)
    const float* Wih = (const float*)d_in[1];   // (1024, 512)
    const float* Whh = (const float*)d_in[2];   // (1024, 1024)
    const float* bih = (const float*)d_in[3];   // (1024,)
    const float* bhh = (const float*)d_in[4];   // (1024,)
    float* out = (float*)d_out;                 // (64, 512, 1024)

    cudaFuncSetAttribute(rnn_step_kernel,
                         cudaFuncAttributeMaxDynamicSharedMemorySize, SMEM3);

    zero_cnt_kernel<<<2, SEQ>>>();

    dim3 g1(HID / 64, (BSZ * SEQ) / 64);
    gemm_xw_kernel<<<g1, 128>>>(x, Wih, bih, bhh, out);

    rnn_step_kernel<<<NCTA, 256, SMEM3>>>(Whh, out);

    tanh_kernel<<<(BSZ * SEQ * HID) / (256 * 4), 256>>>(out);
}